// round 8
// baseline (speedup 1.0000x reference)
#include <cuda_runtime.h>

#define NB 8
#define T 16
#define C 256
#define CM 64
#define AA 32
#define HW 784
#define HWC (HW*C)        /* 200704 */
#define X4F (HWC/4)       /* 50176 float4 per frame */
#define PB 196            /* blocks per video: 784 spatial / 4 rows per block */

// Scratch + sync state (allocation-free rule: __device__ globals).
// All state is self-resetting across graph replays:
//  - g_cnt/g_done are monotone, tested mod PB
//  - g_tsum is zeroed by its reader, g_flag reset by the last consumer
__device__ float    g_tsum[NB*T*C];        // spatial sums (atomic accum)
__device__ float    g_coef[NB*T*3*C];      // folded kern*act table
__device__ unsigned g_cnt[NB];
__device__ unsigned g_done[NB];
__device__ unsigned g_flag[NB];

__global__ void __launch_bounds__(256)
tam_fused(const float4* __restrict__ x4, float4* __restrict__ y4,
          const float* __restrict__ gw1, const float* __restrict__ ggam,
          const float* __restrict__ gbet, const float* __restrict__ gmean,
          const float* __restrict__ gvar, const float* __restrict__ gw2,
          const float* __restrict__ lw1, const float* __restrict__ lgam,
          const float* __restrict__ lbet, const float* __restrict__ lmean,
          const float* __restrict__ lvar, const float* __restrict__ lw2) {
    __shared__ float sh[T*C];      // 16 KB: phase-1 reduce buf (first 4KB) / theta
    __shared__ float red2[256];
    __shared__ float lsig[CM];
    __shared__ unsigned s_last;

    int bid = blockIdx.x;
    int b   = bid / PB;            // video
    int pb  = bid % PB;            // spatial tile (video-contiguous bids)
    int tid = threadIdx.x;
    int c4  = tid & 63, pi = tid >> 6;

    const float4* xp = x4 + (size_t)(b*T)*X4F + (size_t)(pb*4 + pi)*64 + c4;

    // ---------------- Phase 1: spatial partial sums for this slice ----------
    {
        float4* buf4 = (float4*)sh;
        #pragma unroll
        for (int batch = 0; batch < 2; batch++) {
            float4 v[8];
            #pragma unroll
            for (int i = 0; i < 8; i++) v[i] = xp[(size_t)(batch*8 + i)*X4F];
            #pragma unroll
            for (int i = 0; i < 8; i++) {
                buf4[tid] = v[i];
                __syncthreads();
                if (tid < 64) {
                    float4 a = buf4[tid], e = buf4[tid+64],
                           f = buf4[tid+128], g = buf4[tid+192];
                    float* dst = &g_tsum[(size_t)(b*T + batch*8 + i)*C + tid*4];
                    atomicAdd(dst+0, a.x+e.x+f.x+g.x);
                    atomicAdd(dst+1, a.y+e.y+f.y+g.y);
                    atomicAdd(dst+2, a.z+e.z+f.z+g.z);
                    atomicAdd(dst+3, a.w+e.w+f.w+g.w);
                }
                __syncthreads();
            }
        }
    }
    __threadfence();
    if (tid == 0) {
        unsigned old = atomicAdd(&g_cnt[b], 1u);
        s_last = (((old + 1u) % PB) == 0u) ? 1u : 0u;
    }
    __syncthreads();

    // ---------------- Phase 2 (last block of video only): branch math -------
    if (s_last) {
        __threadfence();                       // acquire all partials
        #pragma unroll
        for (int t = 0; t < T; t++) {
            size_t idx = (size_t)(b*T + t)*C + tid;
            float s = g_tsum[idx];
            sh[t*C + tid] = s * (1.0f/(float)HW);   // theta
            g_tsum[idx] = 0.f;                      // reset for next replay
        }
        __syncthreads();
        // global branch (per channel c = tid): Dense(16->32)->bn/relu->Dense(32->3)->softmax
        float kern0, kern1, kern2;
        {
            float th[T];
            #pragma unroll
            for (int t = 0; t < T; t++) th[t] = sh[t*C + tid];
            float lg0 = 0.f, lg1 = 0.f, lg2 = 0.f;
            #pragma unroll 4
            for (int a = 0; a < AA; a++) {
                float g = 0.f;
                #pragma unroll
                for (int t = 0; t < T; t++) g += th[t] * gw1[t*AA + a];
                float inv = rsqrtf(gvar[a] + 1e-3f);
                g = (g - gmean[a]) * (ggam[a] * inv) + gbet[a];
                g = fmaxf(g, 0.f);
                lg0 += g * gw2[a*3 + 0];
                lg1 += g * gw2[a*3 + 1];
                lg2 += g * gw2[a*3 + 2];
            }
            float mx = fmaxf(lg0, fmaxf(lg1, lg2));
            float e0 = expf(lg0 - mx), e1 = expf(lg1 - mx), e2 = expf(lg2 - mx);
            float inv = 1.f/(e0 + e1 + e2);
            kern0 = e0*inv; kern1 = e1*inv; kern2 = e2*inv;
        }
        // local branch per source time ts; fold into coef[t][k][c] = kern_k*act[ts]
        for (int ts = 0; ts < T; ts++) {
            int m = tid & 63, part = tid >> 6;
            float acc = 0.f;
            #pragma unroll 8
            for (int i = 0; i < 192; i++) {
                int j  = part*192 + i;           // j = dt*256 + cc
                int dt = j >> 8, cc = j & 255;
                int tt = ts + dt - 1;
                float thv = (tt >= 0 && tt < T) ? sh[tt*C + cc] : 0.f;
                acc += thv * lw1[j*CM + m];
            }
            red2[tid] = acc;
            __syncthreads();
            if (tid < CM) {
                float v = red2[tid] + red2[tid+64] + red2[tid+128] + red2[tid+192];
                float inv = rsqrtf(lvar[tid] + 1e-3f);
                v = (v - lmean[tid]) * (lgam[tid] * inv) + lbet[tid];
                lsig[tid] = fmaxf(v, 0.f);
            }
            __syncthreads();
            float o = 0.f;
            #pragma unroll 8
            for (int mm = 0; mm < CM; mm++) o += lsig[mm] * lw2[mm*C + tid];
            float a = 1.f/(1.f + expf(-o));
            #pragma unroll
            for (int k = 0; k < 3; k++) {
                int t = ts + 1 - k;              // output time sourcing ts with tap k
                if (t >= 0 && t < T) {
                    float kk = (k == 0) ? kern0 : ((k == 1) ? kern1 : kern2);
                    g_coef[((size_t)(b*T + t)*3 + k)*C + tid] = kk * a;
                }
            }
            __syncthreads();                     // red2/lsig reuse
        }
        // boundary taps source out-of-range times -> zero
        g_coef[((size_t)(b*T + 0)*3 + 0)*C + tid]  = 0.f;
        g_coef[((size_t)(b*T + 15)*3 + 2)*C + tid] = 0.f;
        __threadfence();
        __syncthreads();
        if (tid == 0) atomicExch(&g_flag[b], 1u);
    }

    // ---------------- Phase 3: wait for this video's coef, then aggregate ---
    if (tid == 0) {
        while (*(volatile unsigned*)&g_flag[b] == 0u) __nanosleep(200);
    }
    __syncthreads();
    __threadfence();                              // acquire coef

    {
        const float4* cf = (const float4*)g_coef;
        size_t cb = (size_t)(b*T)*3*64;           // float4 units
        float4* yp = y4 + (size_t)(b*T)*X4F + (size_t)(pb*4 + pi)*64 + c4;
        float4 z = make_float4(0.f,0.f,0.f,0.f);
        float4 xm = z;
        float4 xc = xp[0];                        // L1/L2-hot from phase 1
        #pragma unroll
        for (int t = 0; t < T; t++) {
            float4 xn = (t < T-1) ? xp[(size_t)(t+1)*X4F] : z;
            float4 c0 = cf[cb + ((size_t)t*3 + 0)*64 + c4];
            float4 c1 = cf[cb + ((size_t)t*3 + 1)*64 + c4];
            float4 c2 = cf[cb + ((size_t)t*3 + 2)*64 + c4];
            float4 o;
            o.x = c0.x*xm.x + c1.x*xc.x + c2.x*xn.x;
            o.y = c0.y*xm.y + c1.y*xc.y + c2.y*xn.y;
            o.z = c0.z*xm.z + c1.z*xc.z + c2.z*xn.z;
            o.w = c0.w*xm.w + c1.w*xc.w + c2.w*xn.w;
            __stcs(yp + (size_t)t*X4F, o);
            xm = xc; xc = xn;
        }
    }
    __syncthreads();
    if (tid == 0) {
        __threadfence();
        unsigned old = atomicAdd(&g_done[b], 1u);
        if (((old + 1u) % PB) == 0u) atomicExch(&g_flag[b], 0u);  // reset for next replay
    }
}

extern "C" void kernel_launch(void* const* d_in, const int* in_sizes, int n_in,
                              void* d_out, int out_size) {
    const float* x       = (const float*)d_in[0];
    const float* gw1     = (const float*)d_in[1];
    const float* ggamma  = (const float*)d_in[2];
    const float* gbeta   = (const float*)d_in[3];
    const float* gmean   = (const float*)d_in[4];
    const float* gvar    = (const float*)d_in[5];
    const float* gw2     = (const float*)d_in[6];
    const float* lw1     = (const float*)d_in[7];
    const float* lgamma  = (const float*)d_in[8];
    const float* lbeta   = (const float*)d_in[9];
    const float* lmean   = (const float*)d_in[10];
    const float* lvar    = (const float*)d_in[11];
    const float* lw2     = (const float*)d_in[12];
    float* y = (float*)d_out;

    tam_fused<<<NB*PB, 256>>>((const float4*)x, (float4*)y,
                              gw1, ggamma, gbeta, gmean, gvar, gw2,
                              lw1, lgamma, lbeta, lmean, lvar, lw2);
}

// round 9
// speedup vs baseline: 2.7792x; 2.7792x over previous
#include <cuda_runtime.h>

#define NB 8
#define T 16
#define C 256
#define CM 64
#define AA 32
#define HW 784
#define HWC (HW*C)        /* 200704 */
#define X4F (HWC/4)       /* 50176 float4 per frame */
#define NSPLIT 16
#define ROWS_PER_SEG 49   /* 784/16 */
#define BPV (T*NSPLIT)    /* 256 blocks per video in node 1 */

// Scratch (allocation-free rule: __device__ globals)
__device__ float    g_partial[NB*T*NSPLIT*C];  // 2 MB, per-segment frame sums
__device__ float    g_kern[NB*3*C];            // [b][k][c]
__device__ float    g_act[NB*T*C];             // [b][t][c]
__device__ unsigned g_cnt[NB];                 // monotone, tested mod BPV

// ---------------- Node 1: partial sums + last-block-per-video branch -------
__global__ void __launch_bounds__(256)
k_partial_branch(const float4* __restrict__ x4,
        const float* __restrict__ gw1, const float* __restrict__ ggam,
        const float* __restrict__ gbet, const float* __restrict__ gmean,
        const float* __restrict__ gvar, const float* __restrict__ gw2,
        const float* __restrict__ lw1, const float* __restrict__ lgam,
        const float* __restrict__ lbet, const float* __restrict__ lmean,
        const float* __restrict__ lvar, const float* __restrict__ lw2) {
    __shared__ float sh[T*C];        // 16 KB (phase-1 reduce uses first 4 KB)
    __shared__ float red2[256];
    __shared__ float lsig[CM];
    __shared__ unsigned s_last;

    int n = blockIdx.x, s = blockIdx.y, tid = threadIdx.x;
    int b = n >> 4;
    int c4 = tid & 63, pi = tid >> 6;

    // ---- phase 1: this block reduces segment s of frame n (49 rows) ----
    {
        const float4* xp = x4 + (size_t)n*X4F + (size_t)(s*ROWS_PER_SEG + pi)*64 + c4;
        float4 a0 = make_float4(0,0,0,0), a1 = a0, a2 = a0, a3 = a0;
        #pragma unroll
        for (int i = 0; i < 12; i += 4) {
            float4 v0 = xp[(size_t)(i+0)*256];
            float4 v1 = xp[(size_t)(i+1)*256];
            float4 v2 = xp[(size_t)(i+2)*256];
            float4 v3 = xp[(size_t)(i+3)*256];
            a0.x+=v0.x; a0.y+=v0.y; a0.z+=v0.z; a0.w+=v0.w;
            a1.x+=v1.x; a1.y+=v1.y; a1.z+=v1.z; a1.w+=v1.w;
            a2.x+=v2.x; a2.y+=v2.y; a2.z+=v2.z; a2.w+=v2.w;
            a3.x+=v3.x; a3.y+=v3.y; a3.z+=v3.z; a3.w+=v3.w;
        }
        if (pi == 0) {   // 49th row
            float4 v = xp[(size_t)12*256];
            a0.x+=v.x; a0.y+=v.y; a0.z+=v.z; a0.w+=v.w;
        }
        float4 r;
        r.x = (a0.x+a1.x)+(a2.x+a3.x);
        r.y = (a0.y+a1.y)+(a2.y+a3.y);
        r.z = (a0.z+a1.z)+(a2.z+a3.z);
        r.w = (a0.w+a1.w)+(a2.w+a3.w);
        float4* buf4 = (float4*)sh;
        buf4[tid] = r;
        __syncthreads();
        if (pi == 0) {
            float4 p0 = buf4[c4], p1 = buf4[c4+64], p2 = buf4[c4+128], p3 = buf4[c4+192];
            float4 tot;
            tot.x = (p0.x+p1.x)+(p2.x+p3.x);
            tot.y = (p0.y+p1.y)+(p2.y+p3.y);
            tot.z = (p0.z+p1.z)+(p2.z+p3.z);
            tot.w = (p0.w+p1.w)+(p2.w+p3.w);
            ((float4*)g_partial)[((size_t)n*NSPLIT + s)*64 + c4] = tot;
        }
    }
    __threadfence();
    __syncthreads();
    if (tid == 0) {
        unsigned old = atomicAdd(&g_cnt[b], 1u);
        s_last = (((old + 1u) % BPV) == 0u) ? 1u : 0u;
    }
    __syncthreads();
    if (!s_last) return;

    // ---- phase 2 (one block per video): full branch math ----
    __threadfence();                       // acquire all partial writes
    #pragma unroll
    for (int t = 0; t < T; t++) {
        float sum = 0.f;
        #pragma unroll
        for (int ss = 0; ss < NSPLIT; ss++)
            sum += g_partial[((size_t)(b*T + t)*NSPLIT + ss)*C + tid];
        sh[t*C + tid] = sum * (1.0f/(float)HW);    // theta[t][c]
    }
    __syncthreads();

    // global branch per channel c = tid
    {
        float th[T];
        #pragma unroll
        for (int t = 0; t < T; t++) th[t] = sh[t*C + tid];
        float lg0 = 0.f, lg1 = 0.f, lg2 = 0.f;
        #pragma unroll 4
        for (int a = 0; a < AA; a++) {
            float g = 0.f;
            #pragma unroll
            for (int t = 0; t < T; t++) g += th[t] * gw1[t*AA + a];
            float inv = rsqrtf(gvar[a] + 1e-3f);
            g = (g - gmean[a]) * (ggam[a] * inv) + gbet[a];
            g = fmaxf(g, 0.f);
            lg0 += g * gw2[a*3 + 0];
            lg1 += g * gw2[a*3 + 1];
            lg2 += g * gw2[a*3 + 2];
        }
        float mx = fmaxf(lg0, fmaxf(lg1, lg2));
        float e0 = expf(lg0 - mx), e1 = expf(lg1 - mx), e2 = expf(lg2 - mx);
        float inv = 1.f/(e0 + e1 + e2);
        g_kern[(b*3 + 0)*C + tid] = e0*inv;
        g_kern[(b*3 + 1)*C + tid] = e1*inv;
        g_kern[(b*3 + 2)*C + tid] = e2*inv;
    }

    // local branch: for each ts, conv(3,256->64)->bn/relu->conv(1,64->256)->sigmoid
    for (int ts = 0; ts < T; ts++) {
        int m = tid & 63, part = tid >> 6;
        float acc = 0.f;
        #pragma unroll 8
        for (int i = 0; i < 192; i++) {
            int j  = part*192 + i;             // j = dt*256 + cc
            int dt = j >> 8, cc = j & 255;
            int tt = ts + dt - 1;
            float thv = (tt >= 0 && tt < T) ? sh[tt*C + cc] : 0.f;
            acc += thv * lw1[j*CM + m];
        }
        red2[tid] = acc;
        __syncthreads();
        if (tid < CM) {
            float v = red2[tid] + red2[tid+64] + red2[tid+128] + red2[tid+192];
            float inv = rsqrtf(lvar[tid] + 1e-3f);
            v = (v - lmean[tid]) * (lgam[tid] * inv) + lbet[tid];
            lsig[tid] = fmaxf(v, 0.f);
        }
        __syncthreads();
        float o = 0.f;
        #pragma unroll 8
        for (int mm = 0; mm < CM; mm++) o += lsig[mm] * lw2[mm*C + tid];
        g_act[(b*T + ts)*C + tid] = 1.f/(1.f + expf(-o));
        __syncthreads();                       // red2/lsig reuse next ts
    }
}

// ---------------- Node 2: gate + adaptive temporal conv (EXACT R2 kernel) --
__global__ void k_agg(const float* __restrict__ x, float* __restrict__ y) {
    int tid = threadIdx.x;
    int b  = (NB - 1) - blockIdx.y;
    int pb = (gridDim.x - 1) - blockIdx.x;
    int c4 = tid & 63, pi = tid >> 6;
    int p = pb*4 + pi;
    __shared__ float coef[T*3*C];  // 48 KB
    float k0 = g_kern[(b*3 + 0)*C + tid];
    float k1 = g_kern[(b*3 + 1)*C + tid];
    float k2 = g_kern[(b*3 + 2)*C + tid];
    coef[(0*3 + 0)*C + tid]  = 0.f;
    coef[(15*3 + 2)*C + tid] = 0.f;
    #pragma unroll
    for (int ts = 0; ts < T; ts++) {
        float a = g_act[(b*T + ts)*C + tid];
        #pragma unroll
        for (int k = 0; k < 3; k++) {
            int t = ts + 1 - k;
            if (t >= 0 && t < T) {
                float kk = (k == 0) ? k0 : ((k == 1) ? k1 : k2);
                coef[(t*3 + k)*C + tid] = kk * a;
            }
        }
    }
    __syncthreads();
    const float4* cs4 = (const float4*)coef;
    size_t base4 = ((size_t)(b*T)*HWC + (size_t)p*C) / 4 + c4;
    const float4* xp = (const float4*)x + base4;
    float4*       yp = (float4*)y + base4;
    const int S4 = X4F;
    float4 xm = make_float4(0.f,0.f,0.f,0.f);
    float4 xc = xp[0];
    #pragma unroll
    for (int t = 0; t < T; t++) {
        float4 xn = (t < T-1) ? xp[(size_t)(t+1)*S4] : make_float4(0.f,0.f,0.f,0.f);
        float4 c0 = cs4[(t*3 + 0)*64 + c4];
        float4 c1 = cs4[(t*3 + 1)*64 + c4];
        float4 c2 = cs4[(t*3 + 2)*64 + c4];
        float4 o;
        o.x = c0.x*xm.x + c1.x*xc.x + c2.x*xn.x;
        o.y = c0.y*xm.y + c1.y*xc.y + c2.y*xn.y;
        o.z = c0.z*xm.z + c1.z*xc.z + c2.z*xn.z;
        o.w = c0.w*xm.w + c1.w*xc.w + c2.w*xn.w;
        __stcs(yp + (size_t)t*S4, o);
        xm = xc; xc = xn;
    }
}

extern "C" void kernel_launch(void* const* d_in, const int* in_sizes, int n_in,
                              void* d_out, int out_size) {
    const float* x       = (const float*)d_in[0];
    const float* gw1     = (const float*)d_in[1];
    const float* ggamma  = (const float*)d_in[2];
    const float* gbeta   = (const float*)d_in[3];
    const float* gmean   = (const float*)d_in[4];
    const float* gvar    = (const float*)d_in[5];
    const float* gw2     = (const float*)d_in[6];
    const float* lw1     = (const float*)d_in[7];
    const float* lgamma  = (const float*)d_in[8];
    const float* lbeta   = (const float*)d_in[9];
    const float* lmean   = (const float*)d_in[10];
    const float* lvar    = (const float*)d_in[11];
    const float* lw2     = (const float*)d_in[12];
    float* y = (float*)d_out;

    k_partial_branch<<<dim3(NB*T, NSPLIT), 256>>>((const float4*)x,
                                  gw1, ggamma, gbeta, gmean, gvar, gw2,
                                  lw1, lgamma, lbeta, lmean, lvar, lw2);
    k_agg<<<dim3(HW/4, NB), 256>>>(x, y);
}

// round 10
// speedup vs baseline: 8.3430x; 3.0019x over previous
#include <cuda_runtime.h>

#define NB 8
#define T 16
#define C 256
#define CM 64
#define AA 32
#define HW 784
#define HWC (HW*C)        /* 200704 */
#define X4F (HWC/4)       /* 50176 float4 per frame */
#define NSPLIT 16
#define ROWS_PER_SEG 49   /* 784/16 */

// Scratch (allocation-free rule: __device__ globals)
__device__ float g_partial[NB*T*NSPLIT*C];  // 2 MB
__device__ float g_kern[NB*3*C];            // [b][k][c]
__device__ float g_act[NB*T*C];             // [b][t][c]

// ---------------- K1: spatial partial sums (fold 4 rows in smem) ----------
__global__ void __launch_bounds__(256) k_partial(const float4* __restrict__ x4) {
    __shared__ float4 buf4[256];   // 4 KB
    int n = blockIdx.x, s = blockIdx.y, tid = threadIdx.x;
    int c4 = tid & 63, pi = tid >> 6;
    const float4* xp = x4 + (size_t)n*X4F + (size_t)(s*ROWS_PER_SEG + pi)*64 + c4;
    float4 a0 = make_float4(0,0,0,0), a1 = a0, a2 = a0, a3 = a0;
    #pragma unroll
    for (int i = 0; i < 12; i += 4) {
        float4 v0 = xp[(size_t)(i+0)*256];
        float4 v1 = xp[(size_t)(i+1)*256];
        float4 v2 = xp[(size_t)(i+2)*256];
        float4 v3 = xp[(size_t)(i+3)*256];
        a0.x+=v0.x; a0.y+=v0.y; a0.z+=v0.z; a0.w+=v0.w;
        a1.x+=v1.x; a1.y+=v1.y; a1.z+=v1.z; a1.w+=v1.w;
        a2.x+=v2.x; a2.y+=v2.y; a2.z+=v2.z; a2.w+=v2.w;
        a3.x+=v3.x; a3.y+=v3.y; a3.z+=v3.z; a3.w+=v3.w;
    }
    if (pi == 0) {   // 49th row of the segment
        float4 v = xp[(size_t)12*256];
        a0.x+=v.x; a0.y+=v.y; a0.z+=v.z; a0.w+=v.w;
    }
    float4 r;
    r.x = (a0.x+a1.x)+(a2.x+a3.x);
    r.y = (a0.y+a1.y)+(a2.y+a3.y);
    r.z = (a0.z+a1.z)+(a2.z+a3.z);
    r.w = (a0.w+a1.w)+(a2.w+a3.w);
    buf4[tid] = r;
    __syncthreads();
    if (pi == 0) {
        float4 p0 = buf4[c4], p1 = buf4[c4+64], p2 = buf4[c4+128], p3 = buf4[c4+192];
        float4 tot;
        tot.x = (p0.x+p1.x)+(p2.x+p3.x);
        tot.y = (p0.y+p1.y)+(p2.y+p3.y);
        tot.z = (p0.z+p1.z)+(p2.z+p3.z);
        tot.w = (p0.w+p1.w)+(p2.w+p3.w);
        ((float4*)g_partial)[((size_t)n*NSPLIT + s)*64 + c4] = tot;
    }
}

// ---------------- K2: fused branch kernel (136 blocks, R2-proven) ----------
__global__ void k_branch(const float* __restrict__ gw1, const float* __restrict__ ggam,
                         const float* __restrict__ gbet, const float* __restrict__ gmean,
                         const float* __restrict__ gvar, const float* __restrict__ gw2,
                         const float* __restrict__ lw1, const float* __restrict__ lgam,
                         const float* __restrict__ lbet, const float* __restrict__ lmean,
                         const float* __restrict__ lvar, const float* __restrict__ lw2) {
    cudaGridDependencySynchronize();   // PDL: wait for k_partial's writes
    int bid = blockIdx.x, tid = threadIdx.x;
    if (bid < NB*T) {
        // local branch: conv(3,256->64)->bn/relu->conv(1,64->256)->sigmoid
        int b = bid / T, t = bid % T;
        __shared__ float th_s[3*C];
        __shared__ float red[256];
        __shared__ float l_s[CM];
        #pragma unroll
        for (int dt = 0; dt < 3; dt++) {
            int tt = t + dt - 1;
            float s = 0.f;
            if (tt >= 0 && tt < T) {
                #pragma unroll
                for (int ss = 0; ss < NSPLIT; ss++)
                    s += g_partial[((size_t)(b*T + tt)*NSPLIT + ss)*C + tid];
                s *= (1.0f/(float)HW);
            }
            th_s[dt*C + tid] = s;
        }
        __syncthreads();
        int m = tid & 63, part = tid >> 6;
        float acc = 0.f;
        #pragma unroll 8
        for (int i = 0; i < 192; i++) {
            int j = part*192 + i;                 // j = dt*256 + c
            acc += th_s[j] * lw1[j*CM + m];
        }
        red[tid] = acc;
        __syncthreads();
        if (tid < CM) {
            float v = red[tid] + red[tid+64] + red[tid+128] + red[tid+192];
            float inv = rsqrtf(lvar[tid] + 1e-3f);
            v = (v - lmean[tid]) * (lgam[tid] * inv) + lbet[tid];
            l_s[tid] = fmaxf(v, 0.f);
        }
        __syncthreads();
        float o = 0.f;
        #pragma unroll 8
        for (int mm = 0; mm < CM; mm++) o += l_s[mm] * lw2[mm*C + tid];
        g_act[(b*T + t)*C + tid] = 1.f/(1.f + expf(-o));
    } else {
        // global branch: Dense(16->32)->bn/relu->Dense(32->3)->softmax
        int b = bid - NB*T, c = tid;
        float th[T];
        #pragma unroll
        for (int t = 0; t < T; t++) {
            float s = 0.f;
            #pragma unroll
            for (int ss = 0; ss < NSPLIT; ss++)
                s += g_partial[((size_t)(b*T + t)*NSPLIT + ss)*C + c];
            th[t] = s * (1.0f/(float)HW);
        }
        float lg0 = 0.f, lg1 = 0.f, lg2 = 0.f;
        #pragma unroll 4
        for (int a = 0; a < AA; a++) {
            float g = 0.f;
            #pragma unroll
            for (int t = 0; t < T; t++) g += th[t] * gw1[t*AA + a];
            float inv = rsqrtf(gvar[a] + 1e-3f);
            g = (g - gmean[a]) * (ggam[a] * inv) + gbet[a];
            g = fmaxf(g, 0.f);
            lg0 += g * gw2[a*3 + 0];
            lg1 += g * gw2[a*3 + 1];
            lg2 += g * gw2[a*3 + 2];
        }
        float mx = fmaxf(lg0, fmaxf(lg1, lg2));
        float e0 = expf(lg0 - mx), e1 = expf(lg1 - mx), e2 = expf(lg2 - mx);
        float inv = 1.f/(e0 + e1 + e2);
        g_kern[(b*3 + 0)*C + c] = e0*inv;
        g_kern[(b*3 + 1)*C + c] = e1*inv;
        g_kern[(b*3 + 2)*C + c] = e2*inv;
    }
}

// ---------------- K3: gate + adaptive temporal conv, half-time coef --------
// R2 geometry (4 p-rows/block, 256 channels, float4 rotation) but coef held
// for 8 output-times at a time -> smem 24 KB -> ~5 CTAs/SM instead of 4.
__global__ void k_agg(const float* __restrict__ x, float* __restrict__ y) {
    __shared__ float coef[8*3*C];   // 24 KB
    cudaGridDependencySynchronize();   // PDL: wait for k_branch's writes
    int tid = threadIdx.x;
    int b  = (NB - 1) - blockIdx.y;
    int pb = (gridDim.x - 1) - blockIdx.x;
    int c4 = tid & 63, pi = tid >> 6;
    int p = pb*4 + pi;
    float k0 = g_kern[(b*3 + 0)*C + tid];
    float k1 = g_kern[(b*3 + 1)*C + tid];
    float k2 = g_kern[(b*3 + 2)*C + tid];

    const float4* cs4 = (const float4*)coef;
    const int S4 = X4F;
    size_t base4 = ((size_t)(b*T)*HWC + (size_t)p*C) / 4 + c4;
    const float4* xp = (const float4*)x + base4;
    float4*       yp = (float4*)y + base4;
    float4 z = make_float4(0.f,0.f,0.f,0.f);
    float4 xm = z;
    float4 xc = xp[0];

    #pragma unroll
    for (int h = 0; h < 2; h++) {
        // build coef for output times t in [8h, 8h+8)
        #pragma unroll
        for (int i = 0; i < 8; i++) {
            int t = h*8 + i;
            #pragma unroll
            for (int k = 0; k < 3; k++) {
                int ts = t - 1 + k;
                float v = 0.f;
                if (ts >= 0 && ts < T) {
                    float kk = (k == 0) ? k0 : ((k == 1) ? k1 : k2);
                    v = kk * g_act[(b*T + ts)*C + tid];
                }
                coef[(i*3 + k)*C + tid] = v;
            }
        }
        __syncthreads();
        #pragma unroll
        for (int i = 0; i < 8; i++) {
            int t = h*8 + i;
            float4 xn = (t < T-1) ? xp[(size_t)(t+1)*S4] : z;
            float4 c0 = cs4[(i*3 + 0)*64 + c4];
            float4 c1 = cs4[(i*3 + 1)*64 + c4];
            float4 c2 = cs4[(i*3 + 2)*64 + c4];
            float4 o;
            o.x = c0.x*xm.x + c1.x*xc.x + c2.x*xn.x;
            o.y = c0.y*xm.y + c1.y*xc.y + c2.y*xn.y;
            o.z = c0.z*xm.z + c1.z*xc.z + c2.z*xn.z;
            o.w = c0.w*xm.w + c1.w*xc.w + c2.w*xn.w;
            __stcs(yp + (size_t)t*S4, o);
            xm = xc; xc = xn;
        }
        __syncthreads();   // all threads done with this coef half
    }
}

extern "C" void kernel_launch(void* const* d_in, const int* in_sizes, int n_in,
                              void* d_out, int out_size) {
    const float* x       = (const float*)d_in[0];
    const float* gw1     = (const float*)d_in[1];
    const float* ggamma  = (const float*)d_in[2];
    const float* gbeta   = (const float*)d_in[3];
    const float* gmean   = (const float*)d_in[4];
    const float* gvar    = (const float*)d_in[5];
    const float* gw2     = (const float*)d_in[6];
    const float* lw1     = (const float*)d_in[7];
    const float* lgamma  = (const float*)d_in[8];
    const float* lbeta   = (const float*)d_in[9];
    const float* lmean   = (const float*)d_in[10];
    const float* lvar    = (const float*)d_in[11];
    const float* lw2     = (const float*)d_in[12];
    float* y = (float*)d_out;

    // Node 1: plain launch
    k_partial<<<dim3(NB*T, NSPLIT), 256>>>((const float4*)x);

    // Nodes 2 & 3: PDL (programmatic stream serialization) to overlap launch
    // latency with the predecessor's drain; gridDepSync gates correctness.
    cudaLaunchAttribute attr[1];
    attr[0].id = cudaLaunchAttributeProgrammaticStreamSerialization;
    attr[0].val.programmaticStreamSerializationAllowed = 1;

    {
        cudaLaunchConfig_t cfg = {};
        cfg.gridDim  = dim3(NB*T + NB);
        cfg.blockDim = dim3(256);
        cfg.attrs = attr; cfg.numAttrs = 1;
        cudaLaunchKernelEx(&cfg, k_branch, gw1, ggamma, gbeta, gmean, gvar, gw2,
                           lw1, lgamma, lbeta, lmean, lvar, lw2);
    }
    {
        cudaLaunchConfig_t cfg = {};
        cfg.gridDim  = dim3(HW/4, NB);
        cfg.blockDim = dim3(256);
        cfg.attrs = attr; cfg.numAttrs = 1;
        cudaLaunchKernelEx(&cfg, k_agg, x, y);
    }
}